// round 14
// baseline (speedup 1.0000x reference)
#include <cuda_runtime.h>
#include <cstdint>
#include <math.h>

// Problem constants
#define NB   64
#define SEQL 512
#define DIN  256
#define NF   256
#define KSZ  3
#define NJ   768                 // KSZ*NF

#define NCHUNK 4
#define CB     (NB / NCHUNK)     // 16 batches per chunk

// Static device scratch (no allocs allowed)
__device__ float g_Vr [NJ * DIN];              // rna(V)^T   [j][e]
__device__ float g_Bwt[NJ * DIN];              // Bw^T       [j][d]
__device__ float g_Ub [NB * DIN * DIN];        // rna(U * sig_b)  [b][d][e]
__device__ float g_Wt [NB * NF * NJ];          // weights    [b][f][kd] (kd = k*256+d)

// ---------------------------------------------------------------------------
// Helpers
// ---------------------------------------------------------------------------
__device__ __forceinline__ uint32_t smem_u32(const void* p) {
    uint32_t a;
    asm("{ .reg .u64 t; cvta.to.shared.u64 t, %1; cvt.u32.u64 %0, t; }"
        : "=r"(a) : "l"(p));
    return a;
}
__device__ __forceinline__ float rna(float x) {
    uint32_t u;
    asm("cvt.rna.tf32.f32 %0, %1;" : "=r"(u) : "f"(x));
    return __uint_as_float(u);
}
#define CP16(dst, src) \
    asm volatile("cp.async.cg.shared.global [%0], [%1], 16;" :: "r"(dst), "l"(src))
#define CP16Z(dst, src, sz) \
    asm volatile("cp.async.cg.shared.global [%0], [%1], 16, %2;" :: "r"(dst), "l"(src), "r"(sz))
#define CP_COMMIT() asm volatile("cp.async.commit_group;")
#define CP_WAIT1()  asm volatile("cp.async.wait_group 1;" ::: "memory")
#define CP_WAIT0()  asm volatile("cp.async.wait_group 0;" ::: "memory")

#define LDM4(r0, r1, r2, r3, addr) \
    asm volatile("ldmatrix.sync.aligned.m8n8.x4.shared.b16 {%0,%1,%2,%3}, [%4];" \
        : "=r"(r0), "=r"(r1), "=r"(r2), "=r"(r3) : "r"(addr))

// ---------------------------------------------------------------------------
// SMEM stage (32 KB; three stages = 96 KB dynamic):
//   As: 128 rows (M) x 32 floats (K), 128 B/row; 16B chunk c (0..7) of row r
//       at r*128 + ((c ^ (r&7))<<4)                          [16384 B]
//   Bs: 128 rows (N) x 32 floats (K), same layout/swizzle    [16384 B]
// ---------------------------------------------------------------------------
#define STAGE_BYTES 32768
#define NSTAGE      3
#define SMEM_BYTES  (STAGE_BYTES * NSTAGE)

// One BK=32 slab: warp tile 32(M) x 64(N), m16n8k8 tf32, acc[64].
// A operand may be raw fp32: HW mma truncates to tf32 (RZ) — no cvt needed.
__device__ __forceinline__ void tile_mma(float* __restrict__ acc,
                                         uint32_t Aa, uint32_t Ba,
                                         int lane, int wm, int wn)
{
    const uint32_t s     = lane & 7;
    const uint32_t ahalf = (lane >> 4) & 1;        // A: chunk parity
    const uint32_t bhalf = (lane >> 3) & 1;        // B: chunk parity
    const uint32_t abase = Aa + (wm * 32 + (lane & 15)) * 128;
    const uint32_t bbase = Ba + (wn * 64 + ((lane >> 4) & 1) * 8 + (lane & 7)) * 128;

    #pragma unroll
    for (int ks = 0; ks < 4; ++ks) {
        const uint32_t ca = ((2 * ks + ahalf) ^ s) << 4;
        const uint32_t cb = ((2 * ks + bhalf) ^ s) << 4;

        uint32_t a0[4], a1[4];
        LDM4(a0[0], a0[1], a0[2], a0[3], abase + ca);           // rows m..m+15
        LDM4(a1[0], a1[1], a1[2], a1[3], abase + 2048 + ca);    // +16 rows

        uint32_t bf[4][4];
        #pragma unroll
        for (int q = 0; q < 4; ++q)
            LDM4(bf[q][0], bf[q][1], bf[q][2], bf[q][3], bbase + q * 2048 + cb);

        #pragma unroll
        for (int q = 0; q < 4; ++q)
            #pragma unroll
            for (int p = 0; p < 2; ++p) {
                const int ni = 2 * q + p;
                const uint32_t b0 = bf[q][2 * p], b1 = bf[q][2 * p + 1];
                {
                    float* c = &acc[ni * 4];
                    asm volatile(
                        "mma.sync.aligned.m16n8k8.row.col.f32.tf32.tf32.f32 "
                        "{%0,%1,%2,%3}, {%4,%5,%6,%7}, {%8,%9}, {%0,%1,%2,%3};"
                        : "+f"(c[0]), "+f"(c[1]), "+f"(c[2]), "+f"(c[3])
                        : "r"(a0[0]), "r"(a0[1]), "r"(a0[2]), "r"(a0[3]),
                          "r"(b0), "r"(b1));
                }
                {
                    float* c = &acc[(8 + ni) * 4];
                    asm volatile(
                        "mma.sync.aligned.m16n8k8.row.col.f32.tf32.tf32.f32 "
                        "{%0,%1,%2,%3}, {%4,%5,%6,%7}, {%8,%9}, {%0,%1,%2,%3};"
                        : "+f"(c[0]), "+f"(c[1]), "+f"(c[2]), "+f"(c[3])
                        : "r"(a1[0]), "r"(a1[1]), "r"(a1[2]), "r"(a1[3]),
                          "r"(b0), "r"(b1));
                }
            }
    }
}

// ---------------------------------------------------------------------------
// Combined prep (one launch, flattened grid, 256 thr):
//   blocks [0, 192):    g_Vr[j][e]  = rna(V[e][j])      (32x32 tiles)
//   blocks [192, 384):  g_Bwt[j][d] = Bw[d][j]
//   blocks [384, 4480): g_Ub[b][d][e] = rna(U[d][e] * sigmoid(z[b][e]))
// ---------------------------------------------------------------------------
__global__ void prep_all(const float* __restrict__ U, const float* __restrict__ z,
                         const float* __restrict__ V, const float* __restrict__ Bw)
{
    const int bid = blockIdx.x;
    const int t   = (int)threadIdx.x;
    if (bid < 384) {
        __shared__ float tile[32][33];
        const bool isV = (bid < 192);
        const int idx  = isV ? bid : bid - 192;
        const int j0 = (idx % 24) * 32, e0 = (idx / 24) * 32;
        const int tx = t & 31, ty = t >> 5;
        const float* src = isV ? V : Bw;
        float* dst = isV ? g_Vr : g_Bwt;
        #pragma unroll
        for (int i = 0; i < 4; ++i) {
            const int r = ty + i * 8;
            float v = src[(size_t)(e0 + r) * NJ + j0 + tx];
            if (isV) v = rna(v);
            tile[r][tx] = v;
        }
        __syncthreads();
        #pragma unroll
        for (int i = 0; i < 4; ++i) {
            const int r = ty + i * 8;
            dst[(size_t)(j0 + r) * DIN + e0 + tx] = tile[tx][r];
        }
    } else {
        const int q = bid - 384;           // 4096 blocks: b = q>>6, dblk = q&63
        const int b = q >> 6, dblk = q & 63;
        const int d  = dblk * 4 + (t >> 6);
        const int e4 = (t & 63) * 4;
        const float4 u  = *(const float4*)(U + (size_t)d * DIN + e4);
        const float4 zv = *(const float4*)(z + (size_t)b * DIN + e4);
        float4 o;
        o.x = rna(u.x / (1.f + expf(-zv.x)));
        o.y = rna(u.y / (1.f + expf(-zv.y)));
        o.z = rna(u.z / (1.f + expf(-zv.z)));
        o.w = rna(u.w / (1.f + expf(-zv.w)));
        *(float4*)(g_Ub + ((size_t)(b * DIN + d)) * DIN + e4) = o;
    }
}

// ---------------------------------------------------------------------------
// GEMM1 (batch chunk): per b: D[j][d] = sum_e Vr[j][e] * Ub[b][d][e]
//   M = j (6 tiles of 128 over 768), N = d (2 tiles of 128 over 256), K=256
//   epilogue: + Bwt[j][d], rna, store g_Wt[b][f][kq*256+d]  — coalesced in d
// ---------------------------------------------------------------------------
__global__ __launch_bounds__(256, 2)
void gemm_w(int b0)
{
    extern __shared__ char sm[];
    const int b = b0 + blockIdx.z, m0 = blockIdx.x * 128, n0 = blockIdx.y * 128;
    const int kq = m0 >> 8, f0 = m0 & 255;
    const int tid = (int)threadIdx.x, wid = tid >> 5, lane = tid & 31;
    const int gid = lane >> 2, tig = lane & 3, wm = wid & 3, wn = wid >> 2;

    const uint32_t sb = smem_u32(sm);
    const float* Asrc = g_Vr + (size_t)m0 * DIN;                         // [j][e]
    const float* Bsrc = g_Ub + (size_t)b * DIN * DIN + (size_t)n0 * DIN; // [d][e]

    float acc[64];
    #pragma unroll
    for (int i = 0; i < 64; ++i) acc[i] = 0.f;

    auto load = [&](int t) {
        const int e0 = t * 32, st = t % NSTAGE;
        const uint32_t ab = sb + st * STAGE_BYTES;
        const uint32_t bb = ab + 16384;
        #pragma unroll
        for (int i = 0; i < 4; ++i) {
            const int c = tid + i * 256;
            const int r = c >> 3, c4 = c & 7;
            CP16(ab + r * 128 + ((c4 ^ (r & 7)) << 4),
                 Asrc + (size_t)r * DIN + e0 + c4 * 4);
        }
        #pragma unroll
        for (int i = 0; i < 4; ++i) {
            const int c = tid + i * 256;
            const int r = c >> 3, c4 = c & 7;
            CP16(bb + r * 128 + ((c4 ^ (r & 7)) << 4),
                 Bsrc + (size_t)r * DIN + e0 + c4 * 4);
        }
        CP_COMMIT();
    };

    load(0); load(1);
    for (int t = 0; t < 8; ++t) {
        if (t < 7) CP_WAIT1(); else CP_WAIT0();
        __syncthreads();
        if (t + 2 < 8) load(t + 2);
        const uint32_t stg = sb + (t % NSTAGE) * STAGE_BYTES;
        tile_mma(acc, stg, stg + 16384, lane, wm, wn);
    }

    // epilogue: + Bwt, rna, store g_Wt[b][f][kq*256+d] (contiguous in d)
    #pragma unroll
    for (int mi = 0; mi < 2; ++mi)
        #pragma unroll
        for (int h = 0; h < 2; ++h) {
            const int jl = wm * 32 + mi * 16 + gid + 8 * h;   // j within tile
            const int f  = f0 + jl;
            const float* BwRow = g_Bwt + (size_t)(m0 + jl) * DIN + n0;
            float* Wrow = g_Wt + (size_t)b * NF * NJ + (size_t)f * NJ
                        + (size_t)kq * DIN + n0;
            #pragma unroll
            for (int ni = 0; ni < 8; ++ni) {
                const int dl = wn * 64 + ni * 8 + 2 * tig;
                const float2 bw = *(const float2*)(BwRow + dl);
                const float* c = &acc[(mi * 8 + ni) * 4 + 2 * h];
                float2 w;
                w.x = rna(c[0] + bw.x);
                w.y = rna(c[1] + bw.y);
                *(float2*)(Wrow + dl) = w;
            }
        }
}

// ---------------------------------------------------------------------------
// Conv (batch chunk): per b: out[l][f] = relu( sum_kd A[l][kd]*Wt[b][f][kd]+bias )
//   A[l][kd] = x[b] flat at (l-1)*256 + kd, zero outside [0, 512*256)
//   A raw fp32 (HW truncates to tf32); W pre-rounded rna.
//   CTA 128x128, 256 thr (8 warps, 4x2 of 32x64), BK=32, K=768 (24 tiles)
// ---------------------------------------------------------------------------
__global__ __launch_bounds__(256, 2)
void conv_mma(int b0, const float* __restrict__ x,
              const float* __restrict__ bias, float* __restrict__ out)
{
    extern __shared__ char sm[];
    const int b = b0 + blockIdx.z, l0 = blockIdx.y * 128, f0 = blockIdx.x * 128;
    const int tid = (int)threadIdx.x, wid = tid >> 5, lane = tid & 31;
    const int gid = lane >> 2, tig = lane & 3, wm = wid & 3, wn = wid >> 2;

    const uint32_t sb = smem_u32(sm);
    const float* xb = x + (size_t)b * SEQL * DIN;
    const float* Wsrc = g_Wt + ((size_t)b * NF + f0) * NJ;

    float acc[64];
    #pragma unroll
    for (int i = 0; i < 64; ++i) acc[i] = 0.f;

    auto load = [&](int t) {
        const int e0 = t * 32, st = t % NSTAGE;
        const uint32_t ab = sb + st * STAGE_BYTES;
        const uint32_t bb = ab + 16384;
        #pragma unroll
        for (int i = 0; i < 4; ++i) {
            const int c = tid + i * 256;
            const int r = c >> 3, c4 = c & 7;
            const int idx = (l0 + r - 1) * DIN + e0 + c4 * 4;
            const unsigned ok = ((unsigned)idx < (unsigned)(SEQL * DIN));
            const float* src = xb + (ok ? idx : 0);
            CP16Z(ab + r * 128 + ((c4 ^ (r & 7)) << 4), src, ok ? 16u : 0u);
        }
        #pragma unroll
        for (int i = 0; i < 4; ++i) {
            const int c = tid + i * 256;
            const int r = c >> 3, c4 = c & 7;
            CP16(bb + r * 128 + ((c4 ^ (r & 7)) << 4),
                 Wsrc + (size_t)r * NJ + e0 + c4 * 4);
        }
        CP_COMMIT();
    };

    load(0); load(1);
    for (int t = 0; t < 24; ++t) {
        if (t < 23) CP_WAIT1(); else CP_WAIT0();
        __syncthreads();
        if (t + 2 < 24) load(t + 2);
        const uint32_t stg = sb + (t % NSTAGE) * STAGE_BYTES;
        tile_mma(acc, stg, stg + 16384, lane, wm, wn);
    }

    // epilogue: + bias, relu, store (f contiguous)
    #pragma unroll
    for (int mi = 0; mi < 2; ++mi)
        #pragma unroll
        for (int h = 0; h < 2; ++h) {
            const int l = l0 + wm * 32 + mi * 16 + gid + 8 * h;
            float* Orow = out + ((size_t)b * SEQL + l) * NF + f0;
            #pragma unroll
            for (int ni = 0; ni < 8; ++ni) {
                const int fl = wn * 64 + ni * 8 + 2 * tig;
                const float2 bv = *(const float2*)(bias + f0 + fl);
                const float* c = &acc[(mi * 8 + ni) * 4 + 2 * h];
                float2 o;
                o.x = fmaxf(c[0] + bv.x, 0.f);
                o.y = fmaxf(c[1] + bv.y, 0.f);
                *(float2*)(Orow + fl) = o;
            }
        }
}

// ---------------------------------------------------------------------------
// kernel_launch: prep -> {gemm chunks on side stream} ~overlap~ {conv chunks}
// Capture-safe fork/join via events; no device allocation anywhere.
// Inputs: x, z, U, V, B_w, b, kernel_size(ignored; KSZ=3)
// ---------------------------------------------------------------------------
extern "C" void kernel_launch(void* const* d_in, const int* in_sizes, int n_in,
                              void* d_out, int out_size)
{
    (void)in_sizes; (void)n_in; (void)out_size;
    const float* x    = (const float*)d_in[0];
    const float* z    = (const float*)d_in[1];
    const float* U    = (const float*)d_in[2];
    const float* V    = (const float*)d_in[3];
    const float* Bw   = (const float*)d_in[4];
    const float* bias = (const float*)d_in[5];
    float* out = (float*)d_out;

    cudaFuncSetAttribute(gemm_w,   cudaFuncAttributeMaxDynamicSharedMemorySize, SMEM_BYTES);
    cudaFuncSetAttribute(conv_mma, cudaFuncAttributeMaxDynamicSharedMemorySize, SMEM_BYTES);

    cudaStream_t s1;
    cudaStreamCreateWithFlags(&s1, cudaStreamNonBlocking);
    cudaEvent_t eFork, eJoin, eC[NCHUNK];
    cudaEventCreateWithFlags(&eFork, cudaEventDisableTiming);
    cudaEventCreateWithFlags(&eJoin, cudaEventDisableTiming);
    for (int c = 0; c < NCHUNK; ++c)
        cudaEventCreateWithFlags(&eC[c], cudaEventDisableTiming);

    prep_all<<<4480, 256>>>(U, z, V, Bw);

    // fork: side stream joins after prep
    cudaEventRecord(eFork, 0);
    cudaStreamWaitEvent(s1, eFork, 0);

    // gemm chunks on s1, signaling per-chunk completion
    for (int c = 0; c < NCHUNK; ++c) {
        gemm_w<<<dim3(NJ / 128, DIN / 128, CB), 256, SMEM_BYTES, s1>>>(c * CB);
        cudaEventRecord(eC[c], s1);
    }

    // conv chunks on default stream, each gated on its gemm chunk
    for (int c = 0; c < NCHUNK; ++c) {
        cudaStreamWaitEvent(0, eC[c], 0);
        conv_mma<<<dim3(NF / 128, SEQL / 128, CB), 256, SMEM_BYTES>>>(c * CB, x, bias, out);
    }

    // join: default stream already depends on eC[NCHUNK-1], which is the last
    // s1 work; record/wait once more for explicitness.
    cudaEventRecord(eJoin, s1);
    cudaStreamWaitEvent(0, eJoin, 0);
}

// round 16
// speedup vs baseline: 1.0842x; 1.0842x over previous
#include <cuda_runtime.h>
#include <cstdint>
#include <math.h>

// Problem constants
#define NB   64
#define SEQL 512
#define DIN  256
#define NF   256
#define KSZ  3
#define NJ   768                 // KSZ*NF

// Static device scratch (no allocs allowed)
__device__ float g_Vr [NJ * DIN];              // rna(V)^T   [j][e]
__device__ float g_Bwt[NJ * DIN];              // Bw^T       [j][d]
__device__ float g_Ub [NB * DIN * DIN];        // rna(U * sig_b)  [b][d][e]
__device__ float g_Wt [NB * NF * NJ];          // weights    [b][f][kd] (kd = k*256+d)

// ---------------------------------------------------------------------------
// Helpers
// ---------------------------------------------------------------------------
__device__ __forceinline__ uint32_t smem_u32(const void* p) {
    uint32_t a;
    asm("{ .reg .u64 t; cvta.to.shared.u64 t, %1; cvt.u32.u64 %0, t; }"
        : "=r"(a) : "l"(p));
    return a;
}
__device__ __forceinline__ float rna(float x) {
    uint32_t u;
    asm("cvt.rna.tf32.f32 %0, %1;" : "=r"(u) : "f"(x));
    return __uint_as_float(u);
}
#define CP16(dst, src) \
    asm volatile("cp.async.cg.shared.global [%0], [%1], 16;" :: "r"(dst), "l"(src))
#define CP16Z(dst, src, sz) \
    asm volatile("cp.async.cg.shared.global [%0], [%1], 16, %2;" :: "r"(dst), "l"(src), "r"(sz))
#define CP_COMMIT() asm volatile("cp.async.commit_group;")
#define CP_WAIT1()  asm volatile("cp.async.wait_group 1;" ::: "memory")
#define CP_WAIT0()  asm volatile("cp.async.wait_group 0;" ::: "memory")

#define LDM4(r0, r1, r2, r3, addr) \
    asm volatile("ldmatrix.sync.aligned.m8n8.x4.shared.b16 {%0,%1,%2,%3}, [%4];" \
        : "=r"(r0), "=r"(r1), "=r"(r2), "=r"(r3) : "r"(addr))

// ---------------------------------------------------------------------------
// SMEM stage (32 KB; three stages = 96 KB dynamic):
//   As: 128 rows (M) x 32 floats (K), 128 B/row; 16B chunk c (0..7) of row r
//       at r*128 + ((c ^ (r&7))<<4)                          [16384 B]
//   Bs: 128 rows (N) x 32 floats (K), same layout/swizzle    [16384 B]
// ---------------------------------------------------------------------------
#define STAGE_BYTES 32768
#define NSTAGE      3
#define SMEM_BYTES  (STAGE_BYTES * NSTAGE)

// One BK=32 slab: warp tile 32(M) x 64(N), m16n8k8 tf32, acc[64].
// A operand may be raw fp32: HW mma truncates to tf32 (RZ) — no cvt needed.
__device__ __forceinline__ void tile_mma(float* __restrict__ acc,
                                         uint32_t Aa, uint32_t Ba,
                                         int lane, int wm, int wn)
{
    const uint32_t s     = lane & 7;
    const uint32_t ahalf = (lane >> 4) & 1;        // A: chunk parity
    const uint32_t bhalf = (lane >> 3) & 1;        // B: chunk parity
    const uint32_t abase = Aa + (wm * 32 + (lane & 15)) * 128;
    const uint32_t bbase = Ba + (wn * 64 + ((lane >> 4) & 1) * 8 + (lane & 7)) * 128;

    #pragma unroll
    for (int ks = 0; ks < 4; ++ks) {
        const uint32_t ca = ((2 * ks + ahalf) ^ s) << 4;
        const uint32_t cb = ((2 * ks + bhalf) ^ s) << 4;

        uint32_t a0[4], a1[4];
        LDM4(a0[0], a0[1], a0[2], a0[3], abase + ca);           // rows m..m+15
        LDM4(a1[0], a1[1], a1[2], a1[3], abase + 2048 + ca);    // +16 rows

        uint32_t bf[4][4];
        #pragma unroll
        for (int q = 0; q < 4; ++q)
            LDM4(bf[q][0], bf[q][1], bf[q][2], bf[q][3], bbase + q * 2048 + cb);

        #pragma unroll
        for (int q = 0; q < 4; ++q)
            #pragma unroll
            for (int p = 0; p < 2; ++p) {
                const int ni = 2 * q + p;
                const uint32_t b0 = bf[q][2 * p], b1 = bf[q][2 * p + 1];
                {
                    float* c = &acc[ni * 4];
                    asm volatile(
                        "mma.sync.aligned.m16n8k8.row.col.f32.tf32.tf32.f32 "
                        "{%0,%1,%2,%3}, {%4,%5,%6,%7}, {%8,%9}, {%0,%1,%2,%3};"
                        : "+f"(c[0]), "+f"(c[1]), "+f"(c[2]), "+f"(c[3])
                        : "r"(a0[0]), "r"(a0[1]), "r"(a0[2]), "r"(a0[3]),
                          "r"(b0), "r"(b1));
                }
                {
                    float* c = &acc[(8 + ni) * 4];
                    asm volatile(
                        "mma.sync.aligned.m16n8k8.row.col.f32.tf32.tf32.f32 "
                        "{%0,%1,%2,%3}, {%4,%5,%6,%7}, {%8,%9}, {%0,%1,%2,%3};"
                        : "+f"(c[0]), "+f"(c[1]), "+f"(c[2]), "+f"(c[3])
                        : "r"(a1[0]), "r"(a1[1]), "r"(a1[2]), "r"(a1[3]),
                          "r"(b0), "r"(b1));
                }
            }
    }
}

// ---------------------------------------------------------------------------
// Combined prep (one launch, flattened grid, 256 thr):
//   blocks [0, 192):    g_Vr[j][e]  = rna(V[e][j])      (32x32 tiles)
//   blocks [192, 384):  g_Bwt[j][d] = Bw[d][j]
//   blocks [384, 4480): g_Ub[b][d][e] = rna(U[d][e] * sigmoid(z[b][e]))
// ---------------------------------------------------------------------------
__global__ void prep_all(const float* __restrict__ U, const float* __restrict__ z,
                         const float* __restrict__ V, const float* __restrict__ Bw)
{
    const int bid = blockIdx.x;
    const int t   = (int)threadIdx.x;
    if (bid < 384) {
        __shared__ float tile[32][33];
        const bool isV = (bid < 192);
        const int idx  = isV ? bid : bid - 192;
        const int j0 = (idx % 24) * 32, e0 = (idx / 24) * 32;
        const int tx = t & 31, ty = t >> 5;
        const float* src = isV ? V : Bw;
        float* dst = isV ? g_Vr : g_Bwt;
        #pragma unroll
        for (int i = 0; i < 4; ++i) {
            const int r = ty + i * 8;
            float v = src[(size_t)(e0 + r) * NJ + j0 + tx];
            if (isV) v = rna(v);
            tile[r][tx] = v;
        }
        __syncthreads();
        #pragma unroll
        for (int i = 0; i < 4; ++i) {
            const int r = ty + i * 8;
            dst[(size_t)(j0 + r) * DIN + e0 + tx] = tile[tx][r];
        }
    } else {
        const int q = bid - 384;           // 4096 blocks: b = q>>6, dblk = q&63
        const int b = q >> 6, dblk = q & 63;
        const int d  = dblk * 4 + (t >> 6);
        const int e4 = (t & 63) * 4;
        const float4 u  = *(const float4*)(U + (size_t)d * DIN + e4);
        const float4 zv = *(const float4*)(z + (size_t)b * DIN + e4);
        float4 o;
        o.x = rna(u.x / (1.f + expf(-zv.x)));
        o.y = rna(u.y / (1.f + expf(-zv.y)));
        o.z = rna(u.z / (1.f + expf(-zv.z)));
        o.w = rna(u.w / (1.f + expf(-zv.w)));
        *(float4*)(g_Ub + ((size_t)(b * DIN + d)) * DIN + e4) = o;
    }
}

// ---------------------------------------------------------------------------
// GEMM1 (persistent): per b: D[j][d] = sum_e Vr[j][e] * Ub[b][d][e]
//   768 tiles: tt -> b = tt/12, m0 = ((tt%12)>>1)*128 (j), n0 = (tt&1)*128 (d)
//   K=256 (8 BK-tiles). Cross-tile cp.async pipeline (never drains).
//   epilogue: + Bwt[j][d], rna, store g_Wt[b][f][kq*256+d]  — coalesced in d
// ---------------------------------------------------------------------------
#define GW_NT 768
#define GW_KT 8

__global__ __launch_bounds__(256, 2)
void gemm_w()
{
    extern __shared__ char sm[];
    const int tid = (int)threadIdx.x, wid = tid >> 5, lane = tid & 31;
    const int gid = lane >> 2, tig = lane & 3, wm = wid & 3, wn = wid >> 2;
    const uint32_t sb = smem_u32(sm);
    const int G = (int)gridDim.x, bx = (int)blockIdx.x;
    if (bx >= GW_NT) return;
    const int q_end = ((GW_NT - bx + G - 1) / G) * GW_KT;

    int iss_t = bx, iss_k = 0, qi = 0, qc = 0, cons_t = bx;

    auto issue = [&]() {
        const int b = iss_t / 12, rem = iss_t - b * 12;
        const int m0 = (rem >> 1) << 7, n0 = (rem & 1) << 7;
        const float* iA = g_Vr + (size_t)m0 * DIN;
        const float* iB = g_Ub + (size_t)b * DIN * DIN + (size_t)n0 * DIN;
        const int e0 = iss_k * 32;
        const uint32_t ab = sb + (uint32_t)(qi % 3) * STAGE_BYTES;
        const uint32_t bb = ab + 16384;
        #pragma unroll
        for (int i = 0; i < 4; ++i) {
            const int c = tid + i * 256, r = c >> 3, c4 = c & 7;
            CP16(ab + r * 128 + ((c4 ^ (r & 7)) << 4),
                 iA + (size_t)r * DIN + e0 + c4 * 4);
        }
        #pragma unroll
        for (int i = 0; i < 4; ++i) {
            const int c = tid + i * 256, r = c >> 3, c4 = c & 7;
            CP16(bb + r * 128 + ((c4 ^ (r & 7)) << 4),
                 iB + (size_t)r * DIN + e0 + c4 * 4);
        }
        CP_COMMIT();
        ++qi;
        if (++iss_k == GW_KT) { iss_k = 0; iss_t += G; }
    };

    float acc[64];
    #pragma unroll
    for (int i = 0; i < 64; ++i) acc[i] = 0.f;

    if (qi < q_end) issue();
    if (qi < q_end) issue();

    while (qc < q_end) {
        if (qi - qc >= 2) CP_WAIT1(); else CP_WAIT0();
        __syncthreads();
        if (qi < q_end) issue();
        const uint32_t stg = sb + (uint32_t)(qc % 3) * STAGE_BYTES;
        tile_mma(acc, stg, stg + 16384, lane, wm, wn);
        const int kc = qc % GW_KT;
        ++qc;
        if (kc == GW_KT - 1) {
            const int b = cons_t / 12, rem = cons_t - b * 12;
            const int m0 = (rem >> 1) << 7, n0 = (rem & 1) << 7;
            const int kq = m0 >> 8, f0 = m0 & 255;
            #pragma unroll
            for (int mi = 0; mi < 2; ++mi)
                #pragma unroll
                for (int h = 0; h < 2; ++h) {
                    const int jl = wm * 32 + mi * 16 + gid + 8 * h;
                    const int f  = f0 + jl;
                    const float* BwRow = g_Bwt + (size_t)(m0 + jl) * DIN + n0;
                    float* Wrow = g_Wt + (size_t)b * NF * NJ + (size_t)f * NJ
                                + (size_t)kq * DIN + n0;
                    #pragma unroll
                    for (int ni = 0; ni < 8; ++ni) {
                        const int dl = wn * 64 + ni * 8 + 2 * tig;
                        const float2 bw = *(const float2*)(BwRow + dl);
                        const float* c = &acc[(mi * 8 + ni) * 4 + 2 * h];
                        float2 w;
                        w.x = rna(c[0] + bw.x);
                        w.y = rna(c[1] + bw.y);
                        *(float2*)(Wrow + dl) = w;
                    }
                }
            cons_t += G;
            #pragma unroll
            for (int i = 0; i < 64; ++i) acc[i] = 0.f;
        }
    }
}

// ---------------------------------------------------------------------------
// Conv (persistent): per b: out[l][f] = relu( sum_kd A[l][kd]*Wt[b][f][kd]+b )
//   512 tiles: tt -> b = tt>>3, rem = tt&7, f0 = (rem&1)*128, l0 = (rem>>1)*128
//   A[l][kd] = x[b] flat at (l-1)*256 + kd, zero outside [0, 512*256)
//   A raw fp32 (HW truncates to tf32); W pre-rounded rna. K=768 (24 tiles).
// ---------------------------------------------------------------------------
#define CV_NT 512
#define CV_KT 24

__global__ __launch_bounds__(256, 2)
void conv_mma(const float* __restrict__ x,
              const float* __restrict__ bias, float* __restrict__ out)
{
    extern __shared__ char sm[];
    const int tid = (int)threadIdx.x, wid = tid >> 5, lane = tid & 31;
    const int gid = lane >> 2, tig = lane & 3, wm = wid & 3, wn = wid >> 2;
    const uint32_t sb = smem_u32(sm);
    const int G = (int)gridDim.x, bx = (int)blockIdx.x;
    if (bx >= CV_NT) return;
    const int q_end = ((CV_NT - bx + G - 1) / G) * CV_KT;

    int iss_t = bx, iss_k = 0, qi = 0, qc = 0, cons_t = bx;

    auto issue = [&]() {
        const int b = iss_t >> 3, rem = iss_t & 7;
        const int f0 = (rem & 1) << 7, l0 = (rem >> 1) << 7;
        const float* xb = x + (size_t)b * SEQL * DIN;
        const float* Wsrc = g_Wt + ((size_t)b * NF + f0) * NJ;
        const int e0 = iss_k * 32;
        const uint32_t ab = sb + (uint32_t)(qi % 3) * STAGE_BYTES;
        const uint32_t bb = ab + 16384;
        #pragma unroll
        for (int i = 0; i < 4; ++i) {
            const int c = tid + i * 256, r = c >> 3, c4 = c & 7;
            const int idx = (l0 + r - 1) * DIN + e0 + c4 * 4;
            const unsigned ok = ((unsigned)idx < (unsigned)(SEQL * DIN));
            const float* src = xb + (ok ? idx : 0);
            CP16Z(ab + r * 128 + ((c4 ^ (r & 7)) << 4), src, ok ? 16u : 0u);
        }
        #pragma unroll
        for (int i = 0; i < 4; ++i) {
            const int c = tid + i * 256, r = c >> 3, c4 = c & 7;
            CP16(bb + r * 128 + ((c4 ^ (r & 7)) << 4),
                 Wsrc + (size_t)r * NJ + e0 + c4 * 4);
        }
        CP_COMMIT();
        ++qi;
        if (++iss_k == CV_KT) { iss_k = 0; iss_t += G; }
    };

    float acc[64];
    #pragma unroll
    for (int i = 0; i < 64; ++i) acc[i] = 0.f;

    if (qi < q_end) issue();
    if (qi < q_end) issue();

    while (qc < q_end) {
        if (qi - qc >= 2) CP_WAIT1(); else CP_WAIT0();
        __syncthreads();
        if (qi < q_end) issue();
        const uint32_t stg = sb + (uint32_t)(qc % 3) * STAGE_BYTES;
        tile_mma(acc, stg, stg + 16384, lane, wm, wn);
        const int kc = qc % CV_KT;
        ++qc;
        if (kc == CV_KT - 1) {
            const int b = cons_t >> 3, rem = cons_t & 7;
            const int f0 = (rem & 1) << 7, l0 = (rem >> 1) << 7;
            #pragma unroll
            for (int mi = 0; mi < 2; ++mi)
                #pragma unroll
                for (int h = 0; h < 2; ++h) {
                    const int l = l0 + wm * 32 + mi * 16 + gid + 8 * h;
                    float* Orow = out + ((size_t)b * SEQL + l) * NF + f0;
                    #pragma unroll
                    for (int ni = 0; ni < 8; ++ni) {
                        const int fl = wn * 64 + ni * 8 + 2 * tig;
                        const float2 bv = *(const float2*)(bias + f0 + fl);
                        const float* c = &acc[(mi * 8 + ni) * 4 + 2 * h];
                        float2 o;
                        o.x = fmaxf(c[0] + bv.x, 0.f);
                        o.y = fmaxf(c[1] + bv.y, 0.f);
                        *(float2*)(Orow + fl) = o;
                    }
                }
            cons_t += G;
            #pragma unroll
            for (int i = 0; i < 64; ++i) acc[i] = 0.f;
        }
    }
}

// ---------------------------------------------------------------------------
// kernel_launch: prep_all -> gemm_w -> conv (single stream, capturable)
// Inputs: x, z, U, V, B_w, b, kernel_size(ignored; KSZ=3)
// ---------------------------------------------------------------------------
extern "C" void kernel_launch(void* const* d_in, const int* in_sizes, int n_in,
                              void* d_out, int out_size)
{
    (void)in_sizes; (void)n_in; (void)out_size;
    const float* x    = (const float*)d_in[0];
    const float* z    = (const float*)d_in[1];
    const float* U    = (const float*)d_in[2];
    const float* V    = (const float*)d_in[3];
    const float* Bw   = (const float*)d_in[4];
    const float* bias = (const float*)d_in[5];
    float* out = (float*)d_out;

    static int nper = 0;
    if (nper == 0) {
        cudaFuncSetAttribute(gemm_w,   cudaFuncAttributeMaxDynamicSharedMemorySize, SMEM_BYTES);
        cudaFuncSetAttribute(conv_mma, cudaFuncAttributeMaxDynamicSharedMemorySize, SMEM_BYTES);
        int smc = 148;
        cudaDeviceGetAttribute(&smc, cudaDevAttrMultiProcessorCount, 0);
        nper = 2 * smc;
    }
    const int gG = nper < GW_NT ? nper : GW_NT;
    const int gC = nper < CV_NT ? nper : CV_NT;

    prep_all<<<4480, 256>>>(U, z, V, Bw);
    gemm_w<<<gG, 256, SMEM_BYTES>>>();
    conv_mma<<<gC, 256, SMEM_BYTES>>>(x, bias, out);
}